// round 16
// baseline (speedup 1.0000x reference)
#include <cuda_runtime.h>
#include <cuda_fp16.h>
#include <math.h>
#include <cstdint>

constexpr int BB = 2;
constexpr int SS = 2048;
constexpr int EE = 1024;
constexpr int DD = 1024;
constexpr int HH = 16;
constexpr int HD = 64;
constexpr int MTOK = BB * SS;   // 4096

// ---------------- device scratch ----------------
__device__ __half g_xhi[MTOK * EE];
__device__ __half g_wh[4][DD * EE];             // [0..2]=Wq,Wk,Wv stacked, [3]=Wo
__device__ __half g_ahi[MTOK * DD];
__device__ __half g_qhi[MTOK * DD];
__device__ __half g_khi[MTOK * DD];
__device__ __half g_vhi[MTOK * DD];
__device__ float2 g_tab[SS * 32];
__device__ int g_ctr0;
__device__ int g_ctr1;
__device__ int g_done[32];                      // per (b,qt) head-completion count

// ---------------- PTX helpers ----------------
__device__ __forceinline__ uint32_t smem_u32(const void* p) {
    uint32_t a;
    asm("{ .reg .u64 t; cvta.to.shared.u64 t, %1; cvt.u32.u64 %0, t; }"
        : "=r"(a) : "l"(p));
    return a;
}
__device__ __forceinline__ void cp_async16(uint32_t dst, const void* src) {
    asm volatile("cp.async.cg.shared.global [%0], [%1], 16;"
                 :: "r"(dst), "l"(src) : "memory");
}
#define CP_COMMIT() asm volatile("cp.async.commit_group;" ::: "memory")
#define CP_WAIT2()  asm volatile("cp.async.wait_group 2;" ::: "memory")
#define CP_WAIT1()  asm volatile("cp.async.wait_group 1;" ::: "memory")

__device__ __forceinline__ void ldm_x4(uint32_t& r0, uint32_t& r1, uint32_t& r2,
                                       uint32_t& r3, uint32_t addr) {
    asm volatile("ldmatrix.sync.aligned.m8n8.x4.shared.b16 {%0,%1,%2,%3}, [%4];"
                 : "=r"(r0), "=r"(r1), "=r"(r2), "=r"(r3) : "r"(addr));
}
__device__ __forceinline__ void ldm_x4t(uint32_t& r0, uint32_t& r1, uint32_t& r2,
                                        uint32_t& r3, uint32_t addr) {
    asm volatile("ldmatrix.sync.aligned.m8n8.x4.trans.shared.b16 {%0,%1,%2,%3}, [%4];"
                 : "=r"(r0), "=r"(r1), "=r"(r2), "=r"(r3) : "r"(addr));
}
__device__ __forceinline__ void mma16816(float* c, const uint32_t* a,
                                         uint32_t b0, uint32_t b1) {
    asm volatile(
        "mma.sync.aligned.m16n8k16.row.col.f32.f16.f16.f32 "
        "{%0,%1,%2,%3}, {%4,%5,%6,%7}, {%8,%9}, {%0,%1,%2,%3};"
        : "+f"(c[0]), "+f"(c[1]), "+f"(c[2]), "+f"(c[3])
        : "r"(a[0]), "r"(a[1]), "r"(a[2]), "r"(a[3]), "r"(b0), "r"(b1));
}
__device__ __forceinline__ uint32_t cvt_h2(float lo, float hi) {
    uint32_t r;
    asm("cvt.rn.f16x2.f32 %0, %1, %2;" : "=r"(r) : "f"(hi), "f"(lo));
    return r;
}
__device__ __forceinline__ uint32_t ex2_h2(uint32_t x) {
    uint32_t r;
    asm("ex2.approx.f16x2 %0, %1;" : "=r"(r) : "r"(x));
    return r;
}

// ---------------------------------------------------------------------------
// Fused prologue: x/weights -> fp16, rope table, counter + readiness reset
// ---------------------------------------------------------------------------
__global__ void prologue_fused(const float* __restrict__ x,
                               const float* __restrict__ w0, const float* __restrict__ w1,
                               const float* __restrict__ w2, const float* __restrict__ w3,
                               __half* __restrict__ xhi,
                               __half* __restrict__ wh, float2* __restrict__ tab) {
    int idx = blockIdx.x * blockDim.x + threadIdx.x;
    if (idx == 0) { g_ctr0 = 0; g_ctr1 = 0; }
    if (idx < 32) g_done[idx] = 0;
    constexpr int N0 = MTOK * EE / 4;
    constexpr int PER = DD * EE / 4;
    if (idx < N0) {
        float4 v = ((const float4*)x)[idx];
        ((uint32_t*)xhi)[2 * idx]     = cvt_h2(v.x, v.y);
        ((uint32_t*)xhi)[2 * idx + 1] = cvt_h2(v.z, v.w);
    } else if (idx < N0 + 4 * PER) {
        int j = idx - N0;
        int w = j / PER;
        int jj = j - w * PER;
        const float* s = (w == 0) ? w0 : (w == 1) ? w1 : (w == 2) ? w2 : w3;
        float4 v = ((const float4*)s)[jj];
        uint32_t* o = (uint32_t*)(wh + (size_t)w * PER * 4);
        o[2 * jj]     = cvt_h2(v.x, v.y);
        o[2 * jj + 1] = cvt_h2(v.z, v.w);
    } else {
        int tdx = idx - N0 - 4 * PER;
        if (tdx < SS * 32) {
            int s = tdx >> 5, i = tdx & 31;
            float inv = exp2f(-(float)i * (13.287712379549449f / 32.0f));
            float sn, cs;
            sincosf((float)s * inv, &sn, &cs);
            tab[tdx] = make_float2(cs, sn);
        }
    }
}

// ---------------------------------------------------------------------------
// GEMM core: 1-pass fp16, persistent, 3-buffer ring, one sync per k-step
// ---------------------------------------------------------------------------
constexpr int SAS = 40;
constexpr int GT_B = 128 * SAS * 2;           // 10240
constexpr int GSTG = 2 * GT_B;                // 20480
constexpr int GEMM_SMEM = 3 * GSTG;           // 61440
constexpr int QKV_SMEM = GEMM_SMEM + 16;
constexpr int NKS = 32;
constexpr int NTILES_QKV = 32 * 24;

__device__ __forceinline__ void gemm_mainloop1(
    const __half* __restrict__ A, const __half* __restrict__ B,
    int m0, int n0, uint32_t sb, int tid, int wm, int wn, float acc[2][8][4]) {
    constexpr int K = 1024;
    const int lane = tid & 31;
    const int lrow = tid >> 2;
    const int lseg = tid & 3;
    const int a_r = lane & 15;
    const int a_c = (lane >> 4) * 8;
    const int b_r = (lane & 7) + ((lane >> 4) * 8);
    const int b_c = ((lane >> 3) & 1) * 8;

#pragma unroll
    for (int i = 0; i < 2; i++)
#pragma unroll
        for (int j = 0; j < 8; j++)
#pragma unroll
            for (int u = 0; u < 4; u++) acc[i][j][u] = 0.0f;

    auto issue = [&](int ks) {
        if (ks < NKS) {
            const int k0 = ks << 5;
            const uint32_t st = sb + (ks % 3) * GSTG;
            const uint32_t so = (lrow * SAS + lseg * 8) * 2;
            const size_t ga = (size_t)(m0 + lrow) * K + k0 + lseg * 8;
            cp_async16(st + so, A + ga);
            cp_async16(st + 64 * SAS * 2 + so, A + ga + (size_t)64 * K);
            const size_t gb = (size_t)(n0 + lrow) * K + k0 + lseg * 8;
            cp_async16(st + GT_B + so, B + gb);
            cp_async16(st + GT_B + 64 * SAS * 2 + so, B + gb + (size_t)64 * K);
        }
        CP_COMMIT();
    };

    issue(0);
    issue(1);

    for (int ks = 0; ks < NKS; ks++) {
        CP_WAIT1();
        __syncthreads();
        issue(ks + 2);
        const uint32_t st = sb + (ks % 3) * GSTG;

#pragma unroll
        for (int kt = 0; kt < 2; kt++) {
            uint32_t ah[2][4];
#pragma unroll
            for (int mt = 0; mt < 2; mt++)
                ldm_x4(ah[mt][0], ah[mt][1], ah[mt][2], ah[mt][3],
                       st + ((wm + mt * 16 + a_r) * SAS + kt * 16 + a_c) * 2);
            uint32_t b[8][2];
#pragma unroll
            for (int np = 0; np < 4; np++) {
                uint32_t r0, r1, r2, r3;
                ldm_x4(r0, r1, r2, r3,
                       st + GT_B + ((wn + np * 16 + b_r) * SAS + kt * 16 + b_c) * 2);
                b[np * 2][0] = r0; b[np * 2][1] = r1;
                b[np * 2 + 1][0] = r2; b[np * 2 + 1][1] = r3;
            }
#pragma unroll
            for (int mt = 0; mt < 2; mt++)
#pragma unroll
                for (int nt = 0; nt < 8; nt++)
                    mma16816(acc[mt][nt], ah[mt], b[nt][0], b[nt][1]);
        }
    }
    __syncthreads();
}

// Persistent QKV projection (N=3072), ticket-scheduled; Q scaled by log2e/32.
__global__ __launch_bounds__(256, 2) void gemm_qkv(
    const __half* __restrict__ xhi, const __half* __restrict__ whall,
    const float2* __restrict__ tab,
    __half* __restrict__ qhi, __half* __restrict__ khi, __half* __restrict__ vhi) {
    extern __shared__ char smem[];
    const uint32_t sb = smem_u32(smem);
    int* tix = (int*)(smem + GEMM_SMEM);
    const int tid = threadIdx.x;
    const int wid = tid >> 5;
    const int lane = tid & 31;
    const int wm = (wid & 3) * 32;
    const int wn = (wid >> 2) * 64;
    const int er = lane >> 2;
    const int ec = (lane & 3) * 2;

    for (;;) {
        if (tid == 0) *tix = atomicAdd(&g_ctr0, 1);
        __syncthreads();
        const int t = *tix;
        if (t >= NTILES_QKV) return;

        const int m0 = (t / 24) << 7;
        const int n0 = (t % 24) << 7;
        float acc[2][8][4];
        gemm_mainloop1(xhi, whall, m0, n0, sb, tid, wm, wn, acc);

        const int region = n0 >> 10;
        const float SC = (region == 0) ? 0.045084220027780106f : 1.0f;
        __half* dstp = (region == 0) ? qhi : (region == 1) ? khi : vhi;

#pragma unroll
        for (int mt = 0; mt < 2; mt++) {
#pragma unroll
            for (int nt = 0; nt < 8; nt++) {
                int col = (n0 + wn + nt * 8 + ec) & (DD - 1);
                int h = col >> 6, d = col & 63, i = d >> 1;
#pragma unroll
                for (int r2 = 0; r2 < 2; r2++) {
                    int tok = m0 + wm + mt * 16 + er + r2 * 8;
                    int b = tok >> 11, s = tok & (SS - 1);
                    float c0 = acc[mt][nt][r2 * 2], c1 = acc[mt][nt][r2 * 2 + 1];
                    float r1, rr;
                    if (region < 2) {
                        float2 cssn = tab[s * 32 + i];
                        r1 = (c0 * cssn.x - c1 * cssn.y) * SC;
                        rr = (c0 * cssn.y + c1 * cssn.x) * SC;
                    } else {
                        r1 = c0; rr = c1;
                    }
                    size_t dst = ((size_t)(b * HH + h) * SS + s) * HD + d;
                    *(uint32_t*)&dstp[dst] = cvt_h2(r1, rr);
                }
            }
        }
    }
}

// ---------------------------------------------------------------------------
// Fused persistent attention + output projection.
// Tickets 0..511: attention tiles (descending qt). Tickets 512..767: gemm_o
// tiles gated on per-(b,qt) readiness counters (16 heads each).
// ---------------------------------------------------------------------------
constexpr int APAD = 72;
constexpr int AQH = 0;
constexpr int AST = 128 * APAD * 2;            // 18432
constexpr int AKH = 0, AVH = 9216;
constexpr int ASSZ = 18432;
constexpr int ATTN_BUF = AST + 3 * ASSZ;       // 73728 (gemm part uses [0,61440))
constexpr int ATTN_SMEM = ATTN_BUF + 16;
constexpr int NT_ATTN = 16 * HH * BB;          // 512
constexpr int NT_TOTAL = NT_ATTN + 256;        // + gemm_o tiles

__global__ __launch_bounds__(256, 2) void attn_o(
    const __half* __restrict__ qhi, const __half* __restrict__ khi,
    const __half* __restrict__ vhi, __half* __restrict__ ahi,
    const __half* __restrict__ who, float* __restrict__ out) {
    extern __shared__ char smem[];
    const uint32_t sb = smem_u32(smem);
    int* tix = (int*)(smem + ATTN_BUF);
    const int tid = threadIdx.x;
    const int wid = tid >> 5;
    const int lane = tid & 31;

    const int a_r = lane & 15;
    const int a_c = (lane >> 4) * 8;
    const int b_r = (lane & 7) + ((lane >> 4) * 8);
    const int b_c = ((lane >> 3) & 1) * 8;
    const int vrow = lane & 7;
    const int vmat = lane >> 3;
    const int kr = tid & 63;
    const int ksg = (tid >> 6) * 2;
    const float M2 = 2.8853900817779268f;      // 2 * log2(e)

    for (;;) {
        if (tid == 0) *tix = atomicAdd(&g_ctr1, 1);
        __syncthreads();
        const int t = *tix;
        if (t >= NT_TOTAL) return;

        if (t < NT_ATTN) {
            // ================= attention tile =================
            const int wm = wid * 16;
            const int qt = 15 - (t >> 5);
            const int hb = t & 31;
            const int h = hb & 15;
            const int b = hb >> 4;
            const size_t base = (size_t)(b * HH + h) * SS * HD;
            const int nkt = 2 * qt + 2;

            {
                int row = tid >> 1;
                int sg0 = (tid & 1) * 4;
#pragma unroll
                for (int j = 0; j < 4; j++) {
                    int seg = sg0 + j;
                    cp_async16(sb + AQH + (row * APAD + seg * 8) * 2,
                               qhi + base + (size_t)(qt * 128 + row) * HD + seg * 8);
                }
                CP_COMMIT();
            }

            auto issueKV = [&](int kt) {
                if (kt < nkt) {
                    const uint32_t st = sb + AST + (kt % 3) * ASSZ;
                    const size_t gro = base + (size_t)(kt * 64 + kr) * HD;
#pragma unroll
                    for (int j = 0; j < 2; j++) {
                        int seg = ksg + j;
                        uint32_t so = (kr * APAD + seg * 8) * 2;
                        cp_async16(st + AKH + so, khi + gro + seg * 8);
                        cp_async16(st + AVH + so, vhi + gro + seg * 8);
                    }
                }
                CP_COMMIT();
            };
            issueKV(0);
            issueKV(1);

            CP_WAIT2();
            __syncthreads();

            uint32_t qfh[4][4];
#pragma unroll
            for (int ks = 0; ks < 4; ks++)
                ldm_x4(qfh[ks][0], qfh[ks][1], qfh[ks][2], qfh[ks][3],
                       sb + AQH + ((wm + a_r) * APAD + ks * 16 + a_c) * 2);

            float l_i[2] = {0.0f, 0.0f};
            float o[8][4];
#pragma unroll
            for (int nf = 0; nf < 8; nf++)
#pragma unroll
                for (int e = 0; e < 4; e++) o[nf][e] = 0.0f;

            for (int kt = 0; kt < nkt; kt++) {
                CP_WAIT1();
                __syncthreads();
                issueKV(kt + 2);
                const uint32_t st = sb + AST + (kt % 3) * ASSZ;

                float s[8][4];
#pragma unroll
                for (int nf = 0; nf < 8; nf++)
#pragma unroll
                    for (int e = 0; e < 4; e++) s[nf][e] = -M2;

#pragma unroll
                for (int ks = 0; ks < 4; ks++) {
                    uint32_t bk[8][2];
#pragma unroll
                    for (int np = 0; np < 4; np++) {
                        uint32_t r0, r1, r2, r3;
                        ldm_x4(r0, r1, r2, r3,
                               st + AKH + ((np * 16 + b_r) * APAD + ks * 16 + b_c) * 2);
                        bk[np * 2][0] = r0; bk[np * 2][1] = r1;
                        bk[np * 2 + 1][0] = r2; bk[np * 2 + 1][1] = r3;
                    }
#pragma unroll
                    for (int nf = 0; nf < 8; nf++)
                        mma16816(s[nf], qfh[ks], bk[nf][0], bk[nf][1]);
                }

                if (kt >= 2 * qt) {
                    int row0 = qt * 128 + wm + (lane >> 2);
                    int col0 = kt * 64 + 2 * (lane & 3);
#pragma unroll
                    for (int nf = 0; nf < 8; nf++)
#pragma unroll
                        for (int e = 0; e < 4; e++) {
                            int row = row0 + ((e >> 1) << 3);
                            int col = col0 + nf * 8 + (e & 1);
                            if (col > row) s[nf][e] = -1e30f;
                        }
                }

                uint32_t ph[8][2];
                __half2 lacc[2];
                lacc[0] = __halves2half2(__ushort_as_half(0), __ushort_as_half(0));
                lacc[1] = lacc[0];
#pragma unroll
                for (int nf = 0; nf < 8; nf++) {
#pragma unroll
                    for (int pr = 0; pr < 2; pr++) {
                        uint32_t p = ex2_h2(cvt_h2(s[nf][pr * 2], s[nf][pr * 2 + 1]));
                        ph[nf][pr] = p;
                        lacc[pr] = __hadd2(lacc[pr], *(__half2*)&p);
                    }
                }
#pragma unroll
                for (int pr = 0; pr < 2; pr++) {
                    float2 lf = __half22float2(lacc[pr]);
                    l_i[pr] += lf.x + lf.y;
                }
                uint32_t pah[4][4];
#pragma unroll
                for (int j = 0; j < 4; j++)
#pragma unroll
                    for (int u = 0; u < 4; u++)
                        pah[j][u] = ph[2 * j + (u >> 1)][u & 1];

#pragma unroll
                for (int j = 0; j < 4; j++) {
                    uint32_t bv[8][2];
#pragma unroll
                    for (int dp = 0; dp < 4; dp++) {
                        uint32_t r0, r1, r2, r3;
                        uint32_t addr = st + AVH +
                            ((j * 16 + (vmat & 1) * 8 + vrow) * APAD + dp * 16 + (vmat >> 1) * 8) * 2;
                        ldm_x4t(r0, r1, r2, r3, addr);
                        bv[dp * 2][0] = r0; bv[dp * 2][1] = r1;
                        bv[dp * 2 + 1][0] = r2; bv[dp * 2 + 1][1] = r3;
                    }
#pragma unroll
                    for (int nf = 0; nf < 8; nf++)
                        mma16816(o[nf], pah[j], bv[nf][0], bv[nf][1]);
                }
            }

#pragma unroll
            for (int half = 0; half < 2; half++) {
                l_i[half] += __shfl_xor_sync(0xffffffffu, l_i[half], 1);
                l_i[half] += __shfl_xor_sync(0xffffffffu, l_i[half], 2);
            }
            float inv0 = 1.0f / l_i[0];
            float inv1 = 1.0f / l_i[1];
            int row0 = b * SS + qt * 128 + wid * 16 + (lane >> 2);
            int colb = h * HD + 2 * (lane & 3);
#pragma unroll
            for (int nf = 0; nf < 8; nf++) {
                int col = colb + nf * 8;
                *(uint32_t*)&ahi[(size_t)row0 * DD + col] =
                    cvt_h2(o[nf][0] * inv0, o[nf][1] * inv0);
                *(uint32_t*)&ahi[(size_t)(row0 + 8) * DD + col] =
                    cvt_h2(o[nf][2] * inv1, o[nf][3] * inv1);
            }

            // signal head completion for row-block rb = b*16 + qt
            __syncthreads();
            if (tid == 0) {
                __threadfence();
                atomicAdd(&g_done[b * 16 + qt], 1);
            }
        } else {
            // ================= gemm_o tile =================
            const int to = t - NT_ATTN;
            const int rbi = to >> 3;           // 0..31, readiness order
            const int nx = to & 7;
            const int qt = 15 - (rbi >> 1);
            const int b = rbi & 1;
            const int m0 = b * SS + qt * 128;
            const int n0 = nx << 7;

            if (tid == 0) {
                while (atomicAdd(&g_done[b * 16 + qt], 0) < 16) { }
                __threadfence();
            }
            __syncthreads();

            const int wm = (wid & 3) * 32;
            const int wn = (wid >> 2) * 64;
            float acc[2][8][4];
            gemm_mainloop1(ahi, who, m0, n0, sb, tid, wm, wn, acc);

            const int er = lane >> 2;
            const int ec = (lane & 3) * 2;
#pragma unroll
            for (int mt = 0; mt < 2; mt++) {
                int row = m0 + wm + mt * 16 + er;
#pragma unroll
                for (int nt = 0; nt < 8; nt++) {
                    int col = n0 + wn + nt * 8 + ec;
                    *(float2*)&out[(size_t)row * DD + col] =
                        make_float2(acc[mt][nt][0], acc[mt][nt][1]);
                    *(float2*)&out[(size_t)(row + 8) * DD + col] =
                        make_float2(acc[mt][nt][2], acc[mt][nt][3]);
                }
            }
        }
    }
}

// ---------------------------------------------------------------------------
extern "C" void kernel_launch(void* const* d_in, const int* in_sizes, int n_in,
                              void* d_out, int out_size) {
    const float* x  = (const float*)d_in[0];
    const float* Wq = (const float*)d_in[1];
    const float* Wk = (const float*)d_in[2];
    const float* Wv = (const float*)d_in[3];
    const float* Wo = (const float*)d_in[4];
    float* out = (float*)d_out;

    __half *xhi, *ahi, *qhi, *khi, *vhi;
    __half (*wh)[DD * EE];
    float2* tab;
    cudaGetSymbolAddress((void**)&xhi, g_xhi);
    cudaGetSymbolAddress((void**)&ahi, g_ahi);
    cudaGetSymbolAddress((void**)&wh, g_wh);
    cudaGetSymbolAddress((void**)&qhi, g_qhi);
    cudaGetSymbolAddress((void**)&khi, g_khi);
    cudaGetSymbolAddress((void**)&vhi, g_vhi);
    cudaGetSymbolAddress((void**)&tab, g_tab);

    cudaFuncSetAttribute(gemm_qkv, cudaFuncAttributeMaxDynamicSharedMemorySize, QKV_SMEM);
    cudaFuncSetAttribute(attn_o, cudaFuncAttributeMaxDynamicSharedMemorySize, ATTN_SMEM);

    constexpr int PRO_ITEMS = MTOK * EE / 4 + DD * EE + SS * 32;
    prologue_fused<<<(PRO_ITEMS + 255) / 256, 256>>>(x, Wq, Wk, Wv, Wo,
                                                     xhi, wh[0], tab);

    gemm_qkv<<<296, 256, QKV_SMEM>>>(xhi, wh[0], tab, qhi, khi, vhi);

    attn_o<<<296, 256, ATTN_SMEM>>>(qhi, khi, vhi, ahi, wh[3], out);
}

// round 17
// speedup vs baseline: 1.0295x; 1.0295x over previous
#include <cuda_runtime.h>
#include <cuda_fp16.h>
#include <math.h>
#include <cstdint>

constexpr int BB = 2;
constexpr int SS = 2048;
constexpr int EE = 1024;
constexpr int DD = 1024;
constexpr int HH = 16;
constexpr int HD = 64;
constexpr int MTOK = BB * SS;   // 4096

// ---------------- device scratch ----------------
__device__ __half g_xhi[MTOK * EE];
__device__ __half g_wh[4][DD * EE];             // [0..2]=Wq,Wk,Wv stacked, [3]=Wo
__device__ __half g_ahi[MTOK * DD];
__device__ __half g_qhi[MTOK * DD];
__device__ __half g_khi[MTOK * DD];
__device__ __half g_vhi[MTOK * DD];
__device__ float2 g_tab[SS * 32];
__device__ int g_ctr0;
__device__ int g_ctr1;

// ---------------- PTX helpers ----------------
__device__ __forceinline__ uint32_t smem_u32(const void* p) {
    uint32_t a;
    asm("{ .reg .u64 t; cvta.to.shared.u64 t, %1; cvt.u32.u64 %0, t; }"
        : "=r"(a) : "l"(p));
    return a;
}
__device__ __forceinline__ void cp_async16(uint32_t dst, const void* src) {
    asm volatile("cp.async.cg.shared.global [%0], [%1], 16;"
                 :: "r"(dst), "l"(src) : "memory");
}
#define CP_COMMIT() asm volatile("cp.async.commit_group;" ::: "memory")
#define CP_WAIT2()  asm volatile("cp.async.wait_group 2;" ::: "memory")
#define CP_WAIT1()  asm volatile("cp.async.wait_group 1;" ::: "memory")

__device__ __forceinline__ void ldm_x4(uint32_t& r0, uint32_t& r1, uint32_t& r2,
                                       uint32_t& r3, uint32_t addr) {
    asm volatile("ldmatrix.sync.aligned.m8n8.x4.shared.b16 {%0,%1,%2,%3}, [%4];"
                 : "=r"(r0), "=r"(r1), "=r"(r2), "=r"(r3) : "r"(addr));
}
__device__ __forceinline__ void ldm_x4t(uint32_t& r0, uint32_t& r1, uint32_t& r2,
                                        uint32_t& r3, uint32_t addr) {
    asm volatile("ldmatrix.sync.aligned.m8n8.x4.trans.shared.b16 {%0,%1,%2,%3}, [%4];"
                 : "=r"(r0), "=r"(r1), "=r"(r2), "=r"(r3) : "r"(addr));
}
__device__ __forceinline__ void mma16816(float* c, const uint32_t* a,
                                         uint32_t b0, uint32_t b1) {
    asm volatile(
        "mma.sync.aligned.m16n8k16.row.col.f32.f16.f16.f32 "
        "{%0,%1,%2,%3}, {%4,%5,%6,%7}, {%8,%9}, {%0,%1,%2,%3};"
        : "+f"(c[0]), "+f"(c[1]), "+f"(c[2]), "+f"(c[3])
        : "r"(a[0]), "r"(a[1]), "r"(a[2]), "r"(a[3]), "r"(b0), "r"(b1));
}
__device__ __forceinline__ uint32_t cvt_h2(float lo, float hi) {
    uint32_t r;
    asm("cvt.rn.f16x2.f32 %0, %1, %2;" : "=r"(r) : "f"(hi), "f"(lo));
    return r;
}
__device__ __forceinline__ uint32_t ex2_h2(uint32_t x) {
    uint32_t r;
    asm("ex2.approx.f16x2 %0, %1;" : "=r"(r) : "r"(x));
    return r;
}

// ---------------------------------------------------------------------------
// Fused prologue
// ---------------------------------------------------------------------------
__global__ void prologue_fused(const float* __restrict__ x,
                               const float* __restrict__ w0, const float* __restrict__ w1,
                               const float* __restrict__ w2, const float* __restrict__ w3,
                               __half* __restrict__ xhi,
                               __half* __restrict__ wh, float2* __restrict__ tab) {
    int idx = blockIdx.x * blockDim.x + threadIdx.x;
    if (idx == 0) { g_ctr0 = 0; g_ctr1 = 0; }
    constexpr int N0 = MTOK * EE / 4;
    constexpr int PER = DD * EE / 4;
    if (idx < N0) {
        float4 v = ((const float4*)x)[idx];
        ((uint32_t*)xhi)[2 * idx]     = cvt_h2(v.x, v.y);
        ((uint32_t*)xhi)[2 * idx + 1] = cvt_h2(v.z, v.w);
    } else if (idx < N0 + 4 * PER) {
        int j = idx - N0;
        int w = j / PER;
        int jj = j - w * PER;
        const float* s = (w == 0) ? w0 : (w == 1) ? w1 : (w == 2) ? w2 : w3;
        float4 v = ((const float4*)s)[jj];
        uint32_t* o = (uint32_t*)(wh + (size_t)w * PER * 4);
        o[2 * jj]     = cvt_h2(v.x, v.y);
        o[2 * jj + 1] = cvt_h2(v.z, v.w);
    } else {
        int tdx = idx - N0 - 4 * PER;
        if (tdx < SS * 32) {
            int s = tdx >> 5, i = tdx & 31;
            float inv = exp2f(-(float)i * (13.287712379549449f / 32.0f));
            float sn, cs;
            sincosf((float)s * inv, &sn, &cs);
            tab[tdx] = make_float2(cs, sn);
        }
    }
}

// ---------------------------------------------------------------------------
// GEMM core: 1-pass fp16, persistent, 3-buffer ring, one sync per k-step
// ---------------------------------------------------------------------------
constexpr int SAS = 40;
constexpr int GT_B = 128 * SAS * 2;           // 10240
constexpr int GSTG = 2 * GT_B;                // 20480
constexpr int GEMM_SMEM = 3 * GSTG;           // 61440
constexpr int QKV_SMEM = GEMM_SMEM + 16;
constexpr int NKS = 32;
constexpr int NTILES_QKV = 32 * 24;

__device__ __forceinline__ void gemm_mainloop1(
    const __half* __restrict__ A, const __half* __restrict__ B,
    int m0, int n0, uint32_t sb, int tid, int wm, int wn, float acc[2][8][4]) {
    constexpr int K = 1024;
    const int lane = tid & 31;
    const int lrow = tid >> 2;
    const int lseg = tid & 3;
    const int a_r = lane & 15;
    const int a_c = (lane >> 4) * 8;
    const int b_r = (lane & 7) + ((lane >> 4) * 8);
    const int b_c = ((lane >> 3) & 1) * 8;

#pragma unroll
    for (int i = 0; i < 2; i++)
#pragma unroll
        for (int j = 0; j < 8; j++)
#pragma unroll
            for (int u = 0; u < 4; u++) acc[i][j][u] = 0.0f;

    auto issue = [&](int ks) {
        if (ks < NKS) {
            const int k0 = ks << 5;
            const uint32_t st = sb + (ks % 3) * GSTG;
            const uint32_t so = (lrow * SAS + lseg * 8) * 2;
            const size_t ga = (size_t)(m0 + lrow) * K + k0 + lseg * 8;
            cp_async16(st + so, A + ga);
            cp_async16(st + 64 * SAS * 2 + so, A + ga + (size_t)64 * K);
            const size_t gb = (size_t)(n0 + lrow) * K + k0 + lseg * 8;
            cp_async16(st + GT_B + so, B + gb);
            cp_async16(st + GT_B + 64 * SAS * 2 + so, B + gb + (size_t)64 * K);
        }
        CP_COMMIT();
    };

    issue(0);
    issue(1);

    for (int ks = 0; ks < NKS; ks++) {
        CP_WAIT1();
        __syncthreads();
        issue(ks + 2);
        const uint32_t st = sb + (ks % 3) * GSTG;

#pragma unroll
        for (int kt = 0; kt < 2; kt++) {
            uint32_t ah[2][4];
#pragma unroll
            for (int mt = 0; mt < 2; mt++)
                ldm_x4(ah[mt][0], ah[mt][1], ah[mt][2], ah[mt][3],
                       st + ((wm + mt * 16 + a_r) * SAS + kt * 16 + a_c) * 2);
            uint32_t b[8][2];
#pragma unroll
            for (int np = 0; np < 4; np++) {
                uint32_t r0, r1, r2, r3;
                ldm_x4(r0, r1, r2, r3,
                       st + GT_B + ((wn + np * 16 + b_r) * SAS + kt * 16 + b_c) * 2);
                b[np * 2][0] = r0; b[np * 2][1] = r1;
                b[np * 2 + 1][0] = r2; b[np * 2 + 1][1] = r3;
            }
#pragma unroll
            for (int mt = 0; mt < 2; mt++)
#pragma unroll
                for (int nt = 0; nt < 8; nt++)
                    mma16816(acc[mt][nt], ah[mt], b[nt][0], b[nt][1]);
        }
    }
    __syncthreads();
}

// Persistent QKV projection (N=3072), ticket-scheduled; Q scaled by log2e/32.
__global__ __launch_bounds__(256, 2) void gemm_qkv(
    const __half* __restrict__ xhi, const __half* __restrict__ whall,
    const float2* __restrict__ tab,
    __half* __restrict__ qhi, __half* __restrict__ khi, __half* __restrict__ vhi) {
    extern __shared__ char smem[];
    const uint32_t sb = smem_u32(smem);
    int* tix = (int*)(smem + GEMM_SMEM);
    const int tid = threadIdx.x;
    const int wid = tid >> 5;
    const int lane = tid & 31;
    const int wm = (wid & 3) * 32;
    const int wn = (wid >> 2) * 64;
    const int er = lane >> 2;
    const int ec = (lane & 3) * 2;

    for (;;) {
        if (tid == 0) *tix = atomicAdd(&g_ctr0, 1);
        __syncthreads();
        const int t = *tix;
        if (t >= NTILES_QKV) return;

        const int m0 = (t / 24) << 7;
        const int n0 = (t % 24) << 7;
        float acc[2][8][4];
        gemm_mainloop1(xhi, whall, m0, n0, sb, tid, wm, wn, acc);

        const int region = n0 >> 10;
        const float SC = (region == 0) ? 0.045084220027780106f : 1.0f;
        __half* dstp = (region == 0) ? qhi : (region == 1) ? khi : vhi;

#pragma unroll
        for (int mt = 0; mt < 2; mt++) {
#pragma unroll
            for (int nt = 0; nt < 8; nt++) {
                int col = (n0 + wn + nt * 8 + ec) & (DD - 1);
                int h = col >> 6, d = col & 63, i = d >> 1;
#pragma unroll
                for (int r2 = 0; r2 < 2; r2++) {
                    int tok = m0 + wm + mt * 16 + er + r2 * 8;
                    int b = tok >> 11, s = tok & (SS - 1);
                    float c0 = acc[mt][nt][r2 * 2], c1 = acc[mt][nt][r2 * 2 + 1];
                    float r1, rr;
                    if (region < 2) {
                        float2 cssn = tab[s * 32 + i];
                        r1 = (c0 * cssn.x - c1 * cssn.y) * SC;
                        rr = (c0 * cssn.y + c1 * cssn.x) * SC;
                    } else {
                        r1 = c0; rr = c1;
                    }
                    size_t dst = ((size_t)(b * HH + h) * SS + s) * HD + d;
                    *(uint32_t*)&dstp[dst] = cvt_h2(r1, rr);
                }
            }
        }
    }
}

// Output projection: 1-pass fp16, fp32 epilogue (256 tiles, single wave)
__global__ __launch_bounds__(256, 2) void gemm_o(const __half* __restrict__ Ahi,
                                                 const __half* __restrict__ Bhi,
                                                 float* __restrict__ C) {
    extern __shared__ char smem[];
    const uint32_t sb = smem_u32(smem);
    const int tid = threadIdx.x;
    const int wid = tid >> 5;
    const int lane = tid & 31;
    const int wm = (wid & 3) * 32;
    const int wn = (wid >> 2) * 64;
    constexpr int NX = 8;
    const int tiles = (MTOK >> 7) * NX;

    for (int t = blockIdx.x; t < tiles; t += gridDim.x) {
        const int m0 = (t / NX) << 7;
        const int n0 = (t - (t / NX) * NX) << 7;
        float acc[2][8][4];
        gemm_mainloop1(Ahi, Bhi, m0, n0, sb, tid, wm, wn, acc);

        const int er = lane >> 2;
        const int ec = (lane & 3) * 2;
#pragma unroll
        for (int mt = 0; mt < 2; mt++) {
            int row = m0 + wm + mt * 16 + er;
#pragma unroll
            for (int nt = 0; nt < 8; nt++) {
                int col = n0 + wn + nt * 8 + ec;
                *(float2*)&C[(size_t)row * DD + col] =
                    make_float2(acc[mt][nt][0], acc[mt][nt][1]);
                *(float2*)&C[(size_t)(row + 8) * DD + col] =
                    make_float2(acc[mt][nt][2], acc[mt][nt][3]);
            }
        }
    }
}

// ---------------------------------------------------------------------------
// Persistent flash attention (R15 numerics) + next-tile Q prefetch:
// the ticket for tile n+1 is claimed before tile n's epilogue and its Q
// cp.async issued immediately (Q smem is dead then; frags live in regs),
// hiding the Q load latency under the epilogue + loop turnaround.
// ---------------------------------------------------------------------------
constexpr int APAD = 72;
constexpr int AQH = 0;
constexpr int AST = 128 * APAD * 2;            // 18432
constexpr int AKH = 0, AVH = 9216;
constexpr int ASSZ = 18432;
constexpr int ATTN_BUF = AST + 3 * ASSZ;       // 73728
constexpr int ATTN_SMEM = ATTN_BUF + 16;
constexpr int NTILES_ATTN = 16 * HH * BB;      // 512

__global__ __launch_bounds__(256, 2) void attn_mma(
    const __half* __restrict__ qhi, const __half* __restrict__ khi,
    const __half* __restrict__ vhi, __half* __restrict__ ohi) {
    extern __shared__ char smem[];
    const uint32_t sb = smem_u32(smem);
    int* tix = (int*)(smem + ATTN_BUF);
    const int tid = threadIdx.x;
    const int wid = tid >> 5;
    const int lane = tid & 31;
    const int wm = wid * 16;

    const int a_r = lane & 15;
    const int a_c = (lane >> 4) * 8;
    const int b_r = (lane & 7) + ((lane >> 4) * 8);
    const int b_c = ((lane >> 3) & 1) * 8;
    const int vrow = lane & 7;
    const int vmat = lane >> 3;
    const int kr = tid & 63;
    const int ksg = (tid >> 6) * 2;
    const float M2 = 2.8853900817779268f;      // 2 * log2(e)

    // issue the Q tile for ticket tt (distributed across all 256 threads)
    auto issueQ = [&](int tt) {
        const int qt_ = 15 - (tt >> 5);
        const int hb_ = tt & 31;
        const size_t base_ = (size_t)((hb_ >> 4) * HH + (hb_ & 15)) * SS * HD;
        int row = tid >> 1;
        int sg0 = (tid & 1) * 4;
#pragma unroll
        for (int j = 0; j < 4; j++) {
            int seg = sg0 + j;
            cp_async16(sb + AQH + (row * APAD + seg * 8) * 2,
                       qhi + base_ + (size_t)(qt_ * 128 + row) * HD + seg * 8);
        }
        CP_COMMIT();
    };

    // claim first ticket + issue its Q
    if (tid == 0) *tix = atomicAdd(&g_ctr1, 1);
    __syncthreads();
    int t = *tix;
    if (t < NTILES_ATTN) issueQ(t);

    while (t < NTILES_ATTN) {
        const int qt = 15 - (t >> 5);
        const int hb = t & 31;
        const int h = hb & 15;
        const int b = hb >> 4;
        const size_t base = (size_t)(b * HH + h) * SS * HD;
        const int nkt = 2 * qt + 2;

        auto issueKV = [&](int kt) {
            if (kt < nkt) {
                const uint32_t st = sb + AST + (kt % 3) * ASSZ;
                const size_t gro = base + (size_t)(kt * 64 + kr) * HD;
#pragma unroll
                for (int j = 0; j < 2; j++) {
                    int seg = ksg + j;
                    uint32_t so = (kr * APAD + seg * 8) * 2;
                    cp_async16(st + AKH + so, khi + gro + seg * 8);
                    cp_async16(st + AVH + so, vhi + gro + seg * 8);
                }
            }
            CP_COMMIT();
        };
        issueKV(0);
        issueKV(1);

        CP_WAIT2();     // Q complete (KV0, KV1 may be pending)
        __syncthreads();

        uint32_t qfh[4][4];
#pragma unroll
        for (int ks = 0; ks < 4; ks++)
            ldm_x4(qfh[ks][0], qfh[ks][1], qfh[ks][2], qfh[ks][3],
                   sb + AQH + ((wm + a_r) * APAD + ks * 16 + a_c) * 2);

        float l_i[2] = {0.0f, 0.0f};
        float o[8][4];
#pragma unroll
        for (int nf = 0; nf < 8; nf++)
#pragma unroll
            for (int e = 0; e < 4; e++) o[nf][e] = 0.0f;

        for (int kt = 0; kt < nkt; kt++) {
            CP_WAIT1();
            __syncthreads();
            issueKV(kt + 2);
            const uint32_t st = sb + AST + (kt % 3) * ASSZ;

            float s[8][4];
#pragma unroll
            for (int nf = 0; nf < 8; nf++)
#pragma unroll
                for (int e = 0; e < 4; e++) s[nf][e] = -M2;

#pragma unroll
            for (int ks = 0; ks < 4; ks++) {
                uint32_t bk[8][2];
#pragma unroll
                for (int np = 0; np < 4; np++) {
                    uint32_t r0, r1, r2, r3;
                    ldm_x4(r0, r1, r2, r3,
                           st + AKH + ((np * 16 + b_r) * APAD + ks * 16 + b_c) * 2);
                    bk[np * 2][0] = r0; bk[np * 2][1] = r1;
                    bk[np * 2 + 1][0] = r2; bk[np * 2 + 1][1] = r3;
                }
#pragma unroll
                for (int nf = 0; nf < 8; nf++)
                    mma16816(s[nf], qfh[ks], bk[nf][0], bk[nf][1]);
            }

            if (kt >= 2 * qt) {
                int row0 = qt * 128 + wm + (lane >> 2);
                int col0 = kt * 64 + 2 * (lane & 3);
#pragma unroll
                for (int nf = 0; nf < 8; nf++)
#pragma unroll
                    for (int e = 0; e < 4; e++) {
                        int row = row0 + ((e >> 1) << 3);
                        int col = col0 + nf * 8 + (e & 1);
                        if (col > row) s[nf][e] = -1e30f;
                    }
            }

            uint32_t ph[8][2];
            __half2 lacc[2];
            lacc[0] = __halves2half2(__ushort_as_half(0), __ushort_as_half(0));
            lacc[1] = lacc[0];
#pragma unroll
            for (int nf = 0; nf < 8; nf++) {
#pragma unroll
                for (int pr = 0; pr < 2; pr++) {
                    uint32_t p = ex2_h2(cvt_h2(s[nf][pr * 2], s[nf][pr * 2 + 1]));
                    ph[nf][pr] = p;
                    lacc[pr] = __hadd2(lacc[pr], *(__half2*)&p);
                }
            }
#pragma unroll
            for (int pr = 0; pr < 2; pr++) {
                float2 lf = __half22float2(lacc[pr]);
                l_i[pr] += lf.x + lf.y;
            }
            uint32_t pah[4][4];
#pragma unroll
            for (int j = 0; j < 4; j++)
#pragma unroll
                for (int u = 0; u < 4; u++)
                    pah[j][u] = ph[2 * j + (u >> 1)][u & 1];

#pragma unroll
            for (int j = 0; j < 4; j++) {
                uint32_t bv[8][2];
#pragma unroll
                for (int dp = 0; dp < 4; dp++) {
                    uint32_t r0, r1, r2, r3;
                    uint32_t addr = st + AVH +
                        ((j * 16 + (vmat & 1) * 8 + vrow) * APAD + dp * 16 + (vmat >> 1) * 8) * 2;
                    ldm_x4t(r0, r1, r2, r3, addr);
                    bv[dp * 2][0] = r0; bv[dp * 2][1] = r1;
                    bv[dp * 2 + 1][0] = r2; bv[dp * 2 + 1][1] = r3;
                }
#pragma unroll
                for (int nf = 0; nf < 8; nf++)
                    mma16816(o[nf], pah[j], bv[nf][0], bv[nf][1]);
            }
        }

        // claim next ticket + prefetch its Q (Q smem dead: frags in regs)
        __syncthreads();
        if (tid == 0) *tix = atomicAdd(&g_ctr1, 1);
        __syncthreads();
        const int tn = *tix;
        if (tn < NTILES_ATTN) issueQ(tn);

        // epilogue (registers only)
#pragma unroll
        for (int half = 0; half < 2; half++) {
            l_i[half] += __shfl_xor_sync(0xffffffffu, l_i[half], 1);
            l_i[half] += __shfl_xor_sync(0xffffffffu, l_i[half], 2);
        }
        float inv0 = 1.0f / l_i[0];
        float inv1 = 1.0f / l_i[1];
        int row0 = b * SS + qt * 128 + wm + (lane >> 2);
        int colb = h * HD + 2 * (lane & 3);
#pragma unroll
        for (int nf = 0; nf < 8; nf++) {
            int col = colb + nf * 8;
            *(uint32_t*)&ohi[(size_t)row0 * DD + col] =
                cvt_h2(o[nf][0] * inv0, o[nf][1] * inv0);
            *(uint32_t*)&ohi[(size_t)(row0 + 8) * DD + col] =
                cvt_h2(o[nf][2] * inv1, o[nf][3] * inv1);
        }

        t = tn;
    }
}

// ---------------------------------------------------------------------------
extern "C" void kernel_launch(void* const* d_in, const int* in_sizes, int n_in,
                              void* d_out, int out_size) {
    const float* x  = (const float*)d_in[0];
    const float* Wq = (const float*)d_in[1];
    const float* Wk = (const float*)d_in[2];
    const float* Wv = (const float*)d_in[3];
    const float* Wo = (const float*)d_in[4];
    float* out = (float*)d_out;

    __half *xhi, *ahi, *qhi, *khi, *vhi;
    __half (*wh)[DD * EE];
    float2* tab;
    cudaGetSymbolAddress((void**)&xhi, g_xhi);
    cudaGetSymbolAddress((void**)&ahi, g_ahi);
    cudaGetSymbolAddress((void**)&wh, g_wh);
    cudaGetSymbolAddress((void**)&qhi, g_qhi);
    cudaGetSymbolAddress((void**)&khi, g_khi);
    cudaGetSymbolAddress((void**)&vhi, g_vhi);
    cudaGetSymbolAddress((void**)&tab, g_tab);

    cudaFuncSetAttribute(gemm_qkv, cudaFuncAttributeMaxDynamicSharedMemorySize, QKV_SMEM);
    cudaFuncSetAttribute(gemm_o, cudaFuncAttributeMaxDynamicSharedMemorySize, GEMM_SMEM);
    cudaFuncSetAttribute(attn_mma, cudaFuncAttributeMaxDynamicSharedMemorySize, ATTN_SMEM);

    constexpr int PRO_ITEMS = MTOK * EE / 4 + DD * EE + SS * 32;
    prologue_fused<<<(PRO_ITEMS + 255) / 256, 256>>>(x, Wq, Wk, Wv, Wo,
                                                     xhi, wh[0], tab);

    gemm_qkv<<<296, 256, QKV_SMEM>>>(xhi, wh[0], tab, qhi, khi, vhi);

    attn_mma<<<296, 256, ATTN_SMEM>>>(qhi, khi, vhi, ahi);

    gemm_o<<<256, 256, GEMM_SMEM>>>(ahi, wh[3], out);
}